// round 16
// baseline (speedup 1.0000x reference)
#include <cuda_runtime.h>
#include <math.h>

#define HH 768
#define WW 768
#define LL 8
#define PP 36
#define NPIX (HH*WW)
#define CBLK 128            /* pixels per kernC block */
#define CTHR 256            /* threads per kernC block */
#define CPAD 37

#define C_SIGMAP (1.0f / 11.0f)   /* 1/(3+L) */
#define C_LMBDA  0.1f
#define C_NU     0.01f
#define C_TAUU   (1.0f / 6.0f)
#define C_TAUM   (1.0f / 11.0f)   /* 1/(2+PROJ/4) */

// ---- scratch (allocation-free rule: device globals) ----
__device__ float g_p1[NPIX * LL];
__device__ float g_p2[NPIX * LL];
__device__ float g_p3[NPIX * LL];
__device__ float g_mso1[NPIX * LL];   // level-sums of INPUT mu   (kernC -> kernA iter1)
__device__ float g_mso2[NPIX * LL];
__device__ float g_msp1[NPIX * LL];   // mso + tau*levelsum(proj s) (kernC -> kernA iter2)
__device__ float g_msp2[NPIX * LL];
__device__ float g_u [NPIX * LL];
__device__ float g_ub[NPIX * LL];

// K -> (k1,k2) for the upper-triangular combo ordering (k1 outer, k2 inner)
__device__ __host__ constexpr int kk1(int K) {
    int k1 = 0, r = K, c = LL;
    while (r >= c) { r -= c; k1++; c--; }
    return k1;
}
__device__ __host__ constexpr int kk2(int K) {
    int k1 = 0, r = K, c = LL;
    while (r >= c) { r -= c; k1++; c--; }
    return k1 + r;
}

__device__ __forceinline__ void ld8(const float* __restrict__ p, float* v) {
    float4 a = *(const float4*)p;
    float4 b = *(const float4*)(p + 4);
    v[0]=a.x; v[1]=a.y; v[2]=a.z; v[3]=a.w;
    v[4]=b.x; v[5]=b.y; v[6]=b.z; v[7]=b.w;
}
__device__ __forceinline__ void st8(float* __restrict__ p, const float* v) {
    *(float4*)p       = make_float4(v[0], v[1], v[2], v[3]);
    *(float4*)(p + 4) = make_float4(v[4], v[5], v[6], v[7]);
}

// =====================================================================
// Kernel C: PP-field streaming via padded smem transpose.
// 256 threads / 128-pixel tile. Staging: all threads (18 scalars each
// per array). Reduce: component-split — threads 0..127 handle the *1
// fields of pixel t, threads 128..255 the *2 fields (phase-2 proj norm
// reads both buffers in each half, accumulates only its own component).
// Emits: mso = level-sums of input mu
//        msp = mso + tau * level-sums(proj(s - mb))
// =====================================================================
__global__ __launch_bounds__(CTHR)
void kernC(const float* __restrict__ mu1i, const float* __restrict__ mu2i,
           const float* __restrict__ s1i,  const float* __restrict__ s2i,
           const float* __restrict__ mb1i, const float* __restrict__ mb2i,
           float* __restrict__ mso1, float* __restrict__ mso2,
           float* __restrict__ msp1, float* __restrict__ msp2)
{
    __shared__ float bufA[CBLK * CPAD];
    __shared__ float bufB[CBLK * CPAD];

    const int tid  = threadIdx.x;
    const int half = tid >> 7;          // 0: component 1, 1: component 2
    const int p    = tid & 127;         // pixel within tile
    const int pix  = blockIdx.x * CBLK + p;
    const size_t base = (size_t)blockIdx.x * CBLK * PP;

    // ---- phase 1: stage mu1 -> bufA, mu2 -> bufB (all 256 threads) ----
    #pragma unroll
    for (int j = 0; j < 18; j++) {
        int flat = j * CTHR + tid;      // 18*256 = 4608 = 128*36
        int r = flat / PP, c = flat % PP;
        bufA[r * CPAD + c] = __ldcs(mu1i + base + flat);
        bufB[r * CPAD + c] = __ldcs(mu2i + base + flat);
    }
    __syncthreads();

    // ---- reduce 1 (split): half 0 reduces bufA, half 1 reduces bufB ----
    float ms[LL];
    {
        const float* row = (half == 0 ? bufA : bufB) + p * CPAD;
        float d[LL + 1];
        #pragma unroll
        for (int z = 0; z <= LL; z++) d[z] = 0.0f;
        #pragma unroll
        for (int K = 0; K < PP; K++) {
            float v = row[K];
            d[kk1(K)] += v;  d[kk2(K) + 1] -= v;
        }
        float a = 0.0f;
        #pragma unroll
        for (int z = 0; z < LL; z++) { a += d[z]; ms[z] = a; }
    }
    st8((half == 0 ? mso1 : mso2) + pix * LL, ms);
    __syncthreads();   // before buffer reuse

    // ---- phase 2: stage a1 = s1-mb1 -> bufA, a2 = s2-mb2 -> bufB ----
    #pragma unroll
    for (int j = 0; j < 18; j++) {
        int flat = j * CTHR + tid;
        int r = flat / PP, c = flat % PP;
        bufA[r * CPAD + c] = __ldcs(s1i + base + flat) - __ldcs(mb1i + base + flat);
        bufB[r * CPAD + c] = __ldcs(s2i + base + flat) - __ldcs(mb2i + base + flat);
    }
    __syncthreads();

    // ---- reduce 2 (split): both halves read both rows (norm coupling),
    //      accumulate only their own component's difference array ----
    {
        const float* rowA = bufA + p * CPAD;
        const float* rowB = bufB + p * CPAD;
        float d[LL + 1];
        #pragma unroll
        for (int z = 0; z <= LL; z++) d[z] = 0.0f;
        #pragma unroll
        for (int K = 0; K < PP; K++) {
            float a1 = rowA[K];
            float a2 = rowB[K];
            float nr = sqrtf(a1 * a1 + a2 * a2);
            float x  = (half == 0) ? a1 : a2;
            if (nr > C_NU) x *= __fdividef(C_NU, nr);
            d[kk1(K)] += x;  d[kk2(K) + 1] -= x;
        }
        float a = 0.0f, o[LL];
        #pragma unroll
        for (int z = 0; z < LL; z++) {
            a += d[z];
            o[z] = ms[z] + C_TAUM * a;
        }
        st8((half == 0 ? msp1 : msp2) + pix * LL, o);
    }
}

// =====================================================================
// Kernel A: parabola projection.
// MSN=false (iter1): ms inputs are the level-sums directly (mso).
// MSN=true  (iter2): ms inputs are msp; updated-mu level sums are
//   reconstructed in registers: ms[z] = msp[z] - tau * TS[z].
// =====================================================================
template <bool MSN>
__global__ __launch_bounds__(256)
void kernA(const float* __restrict__ ubar,
           const float* __restrict__ p1i, const float* __restrict__ p2i, const float* __restrict__ p3i,
           const float* __restrict__ ms1i, const float* __restrict__ ms2i,
           const float* __restrict__ f,
           float* __restrict__ p1o, float* __restrict__ p2o, float* __restrict__ p3o)
{
    int pix = blockIdx.x * blockDim.x + threadIdx.x;
    if (pix >= NPIX) return;
    int w = pix % WW;
    int h = pix / WW;

    // ---- forward differences of ubar ----
    float U1[LL], U2[LL], U3[LL];
    {
        float ub[LL];
        ld8(ubar + pix * LL, ub);
        if (h < HH - 1) {
            float nb[LL]; ld8(ubar + (pix + WW) * LL, nb);
            #pragma unroll
            for (int z = 0; z < LL; z++) U1[z] = nb[z] - ub[z];
        } else {
            #pragma unroll
            for (int z = 0; z < LL; z++) U1[z] = 0.0f;
        }
        if (w < WW - 1) {
            float nb[LL]; ld8(ubar + (pix + 1) * LL, nb);
            #pragma unroll
            for (int z = 0; z < LL; z++) U2[z] = nb[z] - ub[z];
        } else {
            #pragma unroll
            for (int z = 0; z < LL; z++) U2[z] = 0.0f;
        }
        #pragma unroll
        for (int z = 0; z < LL; z++) U3[z] = (z < LL - 1) ? (ub[z + 1] - ub[z]) : 0.0f;
    }

    // ---- fold p + sigmap*(diff + ms) into U; ms maybe reconstructed ----
    {
        float ms[LL], pv[LL];

        ld8(p1i + pix * LL, pv);
        ld8(ms1i + pix * LL, ms);
        if (MSN) {
            float c[LL + 1];
            c[0] = 0.0f;
            #pragma unroll
            for (int z = 0; z < LL; z++) c[z + 1] = c[z] + pv[z];
            float suf[LL];
            float a = 0.0f;
            #pragma unroll
            for (int z = LL - 1; z >= 0; z--) { a += c[z + 1]; suf[z] = a; }
            float pr = 0.0f;
            #pragma unroll
            for (int z = 0; z < LL; z++) {
                pr += c[z];
                float ts = (float)(z + 1) * suf[z] - (float)(LL - z) * pr;
                ms[z] = ms[z] - C_TAUM * ts;
            }
        }
        #pragma unroll
        for (int z = 0; z < LL; z++) U1[z] = pv[z] + C_SIGMAP * (U1[z] + ms[z]);

        ld8(p2i + pix * LL, pv);
        ld8(ms2i + pix * LL, ms);
        if (MSN) {
            float c[LL + 1];
            c[0] = 0.0f;
            #pragma unroll
            for (int z = 0; z < LL; z++) c[z + 1] = c[z] + pv[z];
            float suf[LL];
            float a = 0.0f;
            #pragma unroll
            for (int z = LL - 1; z >= 0; z--) { a += c[z + 1]; suf[z] = a; }
            float pr = 0.0f;
            #pragma unroll
            for (int z = 0; z < LL; z++) {
                pr += c[z];
                float ts = (float)(z + 1) * suf[z] - (float)(LL - z) * pr;
                ms[z] = ms[z] - C_TAUM * ts;
            }
        }
        #pragma unroll
        for (int z = 0; z < LL; z++) U2[z] = pv[z] + C_SIGMAP * (U2[z] + ms[z]);

        ld8(p3i + pix * LL, pv);
        #pragma unroll
        for (int z = 0; z < LL; z++) U3[z] = pv[z] + C_SIGMAP * U3[z];
    }

    float fv = __ldg(f + pix);

    // ---- cubic parabola projection, results overwrite U in place ----
    #pragma unroll
    for (int z = 0; z < LL; z++) {
        float t    = (float)(z + 1) * (1.0f / (float)LL) - fv;
        float quad = C_LMBDA * t * t;
        float n2   = U1[z] * U1[z] + U2[z] * U2[z];
        float B    = 0.25f * n2 - quad;
        if (U3[z] < B) {
            float y   = U3[z] + quad;
            float nrm = sqrtf(n2);
            float a   = 0.5f * nrm;
            float b   = (2.0f / 3.0f) * (1.0f - 0.5f * y);
            float sb  = sqrtf(fmaxf(-b, 0.0f));
            float sb3 = sb * sb * sb;
            float d   = (b < 0.0f) ? (a - sb3) * (a + sb3) : fmaf(b * b, b, a * a);
            float v;
            if (d < 0.0f) {
                float ca = fminf(fmaxf(__fdividef(a, sb3), -1.0f), 1.0f);
                v = 2.0f * sb * __cosf(acosf(ca) * (1.0f / 3.0f));
            } else {
                float x  = a + sqrtf(d);
                float c  = (x > 0.0f) ? __powf(x, 1.0f / 3.0f) : 0.0f;
                v = (c == 0.0f) ? 0.0f : (c - __fdividef(b, c));
            }
            float r1, r2;
            if (nrm == 0.0f) { r1 = 0.0f; r2 = 0.0f; }
            else {
                float s = __fdividef(2.0f * v, nrm);
                r1 = s * U1[z]; r2 = s * U2[z];
            }
            U1[z] = r1;
            U2[z] = r2;
            U3[z] = 0.25f * (r1 * r1 + r2 * r2) - quad;
        }
    }
    st8(p1o + pix * LL, U1);
    st8(p2o + pix * LL, U2);
    st8(p3o + pix * LL, U3);
}

// =====================================================================
// Kernel B: clipping only (divergence + clamp + over-relaxation).
// =====================================================================
template <bool WRITE_UBAR>
__global__ __launch_bounds__(256)
void kernB(const float* __restrict__ ui,
           const float* __restrict__ p1, const float* __restrict__ p2, const float* __restrict__ p3,
           float* __restrict__ uo, float* __restrict__ ubo)
{
    int pix = blockIdx.x * blockDim.x + threadIdx.x;
    if (pix >= NPIX) return;
    int w = pix % WW;
    int h = pix / WW;

    float uv[LL];  ld8(ui + pix * LL, uv);
    float p1c[LL]; ld8(p1 + pix * LL, p1c);
    float p2c[LL]; ld8(p2 + pix * LL, p2c);
    float p3c[LL]; ld8(p3 + pix * LL, p3c);

    float p1u[LL], p2l[LL];
    if (h > 0) {
        ld8(p1 + (pix - WW) * LL, p1u);
    } else {
        #pragma unroll
        for (int z = 0; z < LL; z++) p1u[z] = 0.0f;
    }
    if (w > 0) {
        ld8(p2 + (pix - 1) * LL, p2l);
    } else {
        #pragma unroll
        for (int z = 0; z < LL; z++) p2l[z] = 0.0f;
    }

    float ch = (h < HH - 1) ? 1.0f : 0.0f;
    float cw = (w < WW - 1) ? 1.0f : 0.0f;

    float un[LL], ubv[LL];
    #pragma unroll
    for (int z = 0; z < LL; z++) {
        float d1 = ch * p1c[z] - p1u[z];
        float d2 = cw * p2c[z] - p2l[z];
        float d3 = ((z < LL - 1) ? p3c[z] : 0.0f) - ((z > 0) ? p3c[z - 1] : 0.0f);
        float v  = uv[z] + C_TAUU * (d1 + d2 + d3);
        v = fminf(fmaxf(v, 0.0f), 1.0f);
        un[z]  = v;
        ubv[z] = 2.0f * v - uv[z];
    }
    st8(uo + pix * LL, un);
    if (WRITE_UBAR) st8(ubo + pix * LL, ubv);
}

// =====================================================================
extern "C" void kernel_launch(void* const* d_in, const int* in_sizes, int n_in,
                              void* d_out, int out_size)
{
    const float* u    = (const float*)d_in[0];
    const float* ubar = (const float*)d_in[1];
    const float* p1   = (const float*)d_in[2];
    const float* p2   = (const float*)d_in[3];
    const float* p3   = (const float*)d_in[4];
    const float* s1   = (const float*)d_in[5];
    const float* s2   = (const float*)d_in[6];
    const float* mu1  = (const float*)d_in[7];
    const float* mu2  = (const float*)d_in[8];
    const float* mb1  = (const float*)d_in[9];
    const float* mb2  = (const float*)d_in[10];
    const float* f    = (const float*)d_in[11];
    float* out = (float*)d_out;

    float *gp1, *gp2, *gp3, *gmso1, *gmso2, *gmsp1, *gmsp2, *gu, *gub;
    cudaGetSymbolAddress((void**)&gp1,   g_p1);
    cudaGetSymbolAddress((void**)&gp2,   g_p2);
    cudaGetSymbolAddress((void**)&gp3,   g_p3);
    cudaGetSymbolAddress((void**)&gmso1, g_mso1);
    cudaGetSymbolAddress((void**)&gmso2, g_mso2);
    cudaGetSymbolAddress((void**)&gmsp1, g_msp1);
    cudaGetSymbolAddress((void**)&gmsp2, g_msp2);
    cudaGetSymbolAddress((void**)&gu,    g_u);
    cudaGetSymbolAddress((void**)&gub,   g_ub);

    dim3 blk(256);
    dim3 grd((NPIX + 255) / 256);
    dim3 cgrd(NPIX / CBLK);

    // all 36-combo streaming isolated here (split-reduce, 256 thr/tile)
    kernC<<<cgrd, CTHR>>>(mu1, mu2, s1, s2, mb1, mb2, gmso1, gmso2, gmsp1, gmsp2);

    // iteration 1
    kernA<false><<<grd, blk>>>(ubar, p1, p2, p3, gmso1, gmso2, f, gp1, gp2, gp3);
    kernB<true><<<grd, blk>>>(u, gp1, gp2, gp3, gu, gub);

    // iteration 2: msn reconstructed in-register from msp + p rows
    kernA<true><<<grd, blk>>>(gub, gp1, gp2, gp3, gmsp1, gmsp2, f, gp1, gp2, gp3);
    kernB<false><<<grd, blk>>>(gu, gp1, gp2, gp3, out, gub);
}